// round 2
// baseline (speedup 1.0000x reference)
#include <cuda_runtime.h>
#include <cuda_bf16.h>

#define BATCH 8
#define SEQ   512
#define DIM   512
#define TSTEP 16
#define DECAY 0.9f
#define THRESH 1.0f

#define NBLOCKS (148 * 8)   // exactly one full-residency wave on 148 SMs
#define NTHREADS 256

// Persistent grid-stride kernel: one full wave of blocks, each thread loops
// over float4 groups. Per group: gather 4 dims from the embedding table,
// sigmoid, 16-step LIF in registers, 16 streaming float4 stores.
__global__ __launch_bounds__(NTHREADS) void spiking_embed_kernel(
    const int*   __restrict__ ids,     // [BATCH, SEQ]
    const float* __restrict__ table,   // [VOCAB, DIM]
    float*       __restrict__ out)     // [BATCH, TSTEP, SEQ, DIM]
{
    const int D4 = DIM / 4;                         // 128 float4 groups per row
    const int total = BATCH * SEQ * D4;             // 524288
    const int stride = NBLOCKS * NTHREADS;          // 303104
    const size_t tstride4 = (size_t)SEQ * DIM / 4;  // float4 stride per timestep

    for (int idx = blockIdx.x * NTHREADS + threadIdx.x; idx < total; idx += stride) {
        int d4 = idx & (D4 - 1);
        int s  = (idx >> 7) & (SEQ - 1);
        int b  = idx >> 16;

        int token = __ldg(ids + b * SEQ + s);
        const float4 e = *reinterpret_cast<const float4*>(
            table + (size_t)token * DIM + d4 * 4);

        // fp32 sigmoid (matches JAX fp32)
        float rx = 1.0f / (1.0f + expf(-e.x));
        float ry = 1.0f / (1.0f + expf(-e.y));
        float rz = 1.0f / (1.0f + expf(-e.z));
        float rw = 1.0f / (1.0f + expf(-e.w));

        float vx = 0.f, vy = 0.f, vz = 0.f, vw = 0.f;

        size_t base = (((size_t)b * TSTEP) * SEQ + s) * (size_t)DIM + (size_t)d4 * 4;
        float4* outp = reinterpret_cast<float4*>(out + base);

        #pragma unroll
        for (int t = 0; t < TSTEP; t++) {
            vx = fmaf(DECAY, vx, rx);
            vy = fmaf(DECAY, vy, ry);
            vz = fmaf(DECAY, vz, rz);
            vw = fmaf(DECAY, vw, rw);
            float4 sp;
            sp.x = (vx >= THRESH) ? 1.0f : 0.0f;
            sp.y = (vy >= THRESH) ? 1.0f : 0.0f;
            sp.z = (vz >= THRESH) ? 1.0f : 0.0f;
            sp.w = (vw >= THRESH) ? 1.0f : 0.0f;
            vx -= sp.x;   // THRESH == 1.0f
            vy -= sp.y;
            vz -= sp.z;
            vw -= sp.w;
            __stcs(outp + (size_t)t * tstride4, sp);   // streaming store
        }
    }
}

extern "C" void kernel_launch(void* const* d_in, const int* in_sizes, int n_in,
                              void* d_out, int out_size) {
    const int*   ids;
    const float* table;
    if (in_sizes[0] == BATCH * SEQ) {
        ids   = (const int*)d_in[0];
        table = (const float*)d_in[1];
    } else {
        ids   = (const int*)d_in[1];
        table = (const float*)d_in[0];
    }
    float* out = (float*)d_out;

    spiking_embed_kernel<<<NBLOCKS, NTHREADS>>>(ids, table, out);
}